// round 7
// baseline (speedup 1.0000x reference)
#include <cuda_runtime.h>
#include <cstdint>

#define D    128
#define C    21
#define CP   132      // padded W-transpose row stride (floats)
#define PROW 32       // padded P-table row (floats) = one 128B line
#define MAXN 50000
#define NPT  8        // nodes per warp in nodeproj

typedef unsigned long long ull;

// Scratch (static device globals — no allocation allowed)
__device__ float g_WsT[C * CP];
__device__ float g_WdT[C * CP];
__device__ float g_bc[C];
__device__ float g_Ps[MAXN * PROW];
__device__ float g_Pd[MAXN * PROW];
__device__ int   g_is64;

// ---- packed fp32x2 ops (sm_103a; PTX-only forms) ---------------------------
__device__ __forceinline__ ull fma2(ull a, ull b, ull c) {
    ull d;
    asm("fma.rn.f32x2 %0, %1, %2, %3;" : "=l"(d) : "l"(a), "l"(b), "l"(c));
    return d;
}
__device__ __forceinline__ ull add2(ull a, ull b) {
    ull d;
    asm("add.rn.f32x2 %0, %1, %2;" : "=l"(d) : "l"(a), "l"(b));
    return d;
}
__device__ __forceinline__ void unpack2(ull v, float& lo, float& hi) {
    uint32_t l, h;
    asm("mov.b64 {%0, %1}, %2;" : "=r"(l), "=r"(h) : "l"(v));
    lo = __uint_as_float(l); hi = __uint_as_float(h);
}
__device__ __forceinline__ ull pack2f(float lo, float hi) {
    ull r;
    asm("mov.b64 %0, {%1, %2};" : "=l"(r)
        : "r"(__float_as_uint(lo)), "r"(__float_as_uint(hi)));
    return r;
}
__device__ __forceinline__ float f2sum(ull v) {
    float lo, hi; unpack2(v, lo, hi); return lo + hi;
}

// ---------------------------------------------------------------------------
// combine_kernel: 4 lanes per output + quad shfl-reduce (84 full compute
// blocks); last block does dtype detection (warp 0) + bias fold.
// ---------------------------------------------------------------------------
__global__ void __launch_bounds__(256) combine_kernel(const float* __restrict__ Wsrc,
                                                      const float* __restrict__ Wdst,
                                                      const float* __restrict__ Wcls,
                                                      const float* __restrict__ bfuse,
                                                      const float* __restrict__ bcls,
                                                      const uint32_t* __restrict__ ew) {
    if (blockIdx.x == gridDim.x - 1) {
        // int64/int32 detection (warp 0)
        if (threadIdx.x < 32) {
            int lane = threadIdx.x;
            uint32_t v = 0;
#pragma unroll
            for (int i = 0; i < 8; i++)
                v |= ew[1 + 2 * (lane + 32 * i)];   // odd words: int64 high halves
#pragma unroll
            for (int o = 16; o; o >>= 1)
                v |= __shfl_xor_sync(0xffffffffu, v, o);
            if (lane == 0) g_is64 = (v == 0u) ? 1 : 0;
        } else if (threadIdx.x < 32 + C) {
            // bias fold: bc = b_fuse @ Wcls + b_cls
            int c = threadIdx.x - 32;
            float acc = bcls[c];
#pragma unroll 4
            for (int j = 0; j < D; j++)
                acc = fmaf(bfuse[j], __ldg(&Wcls[j * C + c]), acc);
            g_bc[c] = acc;
        }
        return;
    }

    __shared__ float sWc[D * C];
    for (int i = threadIdx.x; i < D * C; i += blockDim.x)
        sWc[i] = Wcls[i];
    __syncthreads();

    int t = blockIdx.x * blockDim.x + threadIdx.x;   // 84 blocks * 256 = 21504 = 4*5376
    int o = t >> 2;                                  // output id in [0, 2*D*C)
    int p = t & 3;                                   // quarter of the K dim
    int m = o / (D * C);
    int r = o % (D * C);
    int k = r / C;
    int c = r % C;

    const float4* W4 = (const float4*)((m ? Wdst : Wsrc) + (size_t)k * D) + 8 * p;
    float acc = 0.f;
#pragma unroll
    for (int j = 0; j < 8; j++) {
        float4 w = __ldg(W4 + j);
        int e = 32 * p + 4 * j;
        acc = fmaf(w.x, sWc[(e + 0) * C + c], acc);
        acc = fmaf(w.y, sWc[(e + 1) * C + c], acc);
        acc = fmaf(w.z, sWc[(e + 2) * C + c], acc);
        acc = fmaf(w.w, sWc[(e + 3) * C + c], acc);
    }
    acc += __shfl_down_sync(0xffffffffu, acc, 1);
    acc += __shfl_down_sync(0xffffffffu, acc, 2);
    if (p == 0)
        (m ? g_WdT : g_WsT)[c * CP + k] = acc;
}

// ---------------------------------------------------------------------------
// Per-node projection: warp = NPT nodes x (lane = class), f32x2 FMAs.
// ---------------------------------------------------------------------------
__global__ void __launch_bounds__(256) nodeproj_kernel(const float* __restrict__ emb, int N) {
    __shared__ __align__(16) float sWs[C * CP];
    __shared__ __align__(16) float sWd[C * CP];
    __shared__ float sbc[C];
    for (int i = threadIdx.x; i < C * CP; i += blockDim.x) {
        sWs[i] = g_WsT[i];
        sWd[i] = g_WdT[i];
    }
    if (threadIdx.x < C) sbc[threadIdx.x] = g_bc[threadIdx.x];
    __syncthreads();

    int wid  = threadIdx.x >> 5;
    int lane = threadIdx.x & 31;
    int n0   = (blockIdx.x * 8 + wid) * NPT;
    if (n0 >= N) return;

    int cc = (lane < C) ? lane : (C - 1);
    const ulonglong2* ws2 = (const ulonglong2*)(sWs + cc * CP);
    const ulonglong2* wd2 = (const ulonglong2*)(sWd + cc * CP);
    const ulonglong2* e2  = (const ulonglong2*)(emb + (size_t)n0 * D);

    ull as2[NPT], ad2[NPT];
#pragma unroll
    for (int j = 0; j < NPT; j++) { as2[j] = 0ull; ad2[j] = 0ull; }

    int nv = N - n0; if (nv > NPT) nv = NPT;

    if (nv == NPT) {
#pragma unroll
        for (int k = 0; k < D / 4; k++) {
            ulonglong2 ws = ws2[k];
            ulonglong2 wd = wd2[k];
#pragma unroll
            for (int j = 0; j < NPT; j++) {
                ulonglong2 ev = __ldg(e2 + (size_t)j * (D / 4) + k);  // warp broadcast
                as2[j] = fma2(ev.x, ws.x, as2[j]);
                as2[j] = fma2(ev.y, ws.y, as2[j]);
                ad2[j] = fma2(ev.x, wd.x, ad2[j]);
                ad2[j] = fma2(ev.y, wd.y, ad2[j]);
            }
        }
    } else {
        for (int k = 0; k < D / 4; k++) {
            ulonglong2 ws = ws2[k];
            ulonglong2 wd = wd2[k];
            for (int j = 0; j < nv; j++) {
                ulonglong2 ev = __ldg(e2 + (size_t)j * (D / 4) + k);
                as2[j] = fma2(ev.x, ws.x, as2[j]);
                as2[j] = fma2(ev.y, ws.y, as2[j]);
                ad2[j] = fma2(ev.x, wd.x, ad2[j]);
                ad2[j] = fma2(ev.y, wd.y, ad2[j]);
            }
        }
    }

    if (lane < C) {
        float bc = sbc[lane];
#pragma unroll
        for (int j = 0; j < NPT; j++) {
            if (j < nv) {
                g_Ps[(size_t)(n0 + j) * PROW + lane] = f2sum(as2[j]) + bc;
                g_Pd[(size_t)(n0 + j) * PROW + lane] = f2sum(ad2[j]);
            }
        }
    }
}

// ---------------------------------------------------------------------------
// Edge kernel: half-warp cooperative gathers + single aligned STG.64 flush.
// Per iteration (2 adjacent edges A=2it, B=2it+1):
//  - each 16-lane half gathers one full P row per table via LDG.64 (1 wf/row)
//  - packed f32x2 add
//  - the 42 output floats form one 8B-aligned 168B block; two shfls realign
//    edge B by one float, then ONE STG.64 with 21 active lanes stores the
//    whole block contiguously (~2.3 wf vs ~5 for the scalar-store form).
// ---------------------------------------------------------------------------
__global__ void __launch_bounds__(256) edge_kernel(const uint32_t* __restrict__ ew,
                                                   float* __restrict__ out,
                                                   uint32_t E) {
    const uint32_t F = 0xffffffffu;
    uint32_t wid  = threadIdx.x >> 5;
    uint32_t lane = threadIdx.x & 31;
    uint32_t warp = blockIdx.x * 8u + wid;
    uint32_t e0   = warp * 32u;
    if (e0 >= E) return;

    uint32_t myE = e0 + lane;
    bool have = (myE < E);
    uint32_t sv = 0, dv = 0;
    if (g_is64) {
        const uint2* ew2 = (const uint2*)ew;
        if (have) {
            sv = ew2[myE].x;
            dv = ew2[(size_t)E + myE].x;
        }
    } else {
        if (have) {
            sv = ew[myE];
            dv = ew[(size_t)E + myE];
        }
    }

    const ull* __restrict__ Ps8 = (const ull*)g_Ps;   // row = 16 ulls (128B)
    const ull* __restrict__ Pd8 = (const ull*)g_Pd;

    uint32_t h = lane >> 4;          // half id: edge parity within the pair
    uint32_t q = lane & 15;          // float-pair index within row
    uint32_t nIt = E - e0; if (nIt > 32u) nIt = 32u;

    if (nIt == 32u) {
        ull* outU = (ull*)(out + (size_t)e0 * C);     // warp base: 2688B-aligned
        bool doStore = (lane <= 10u) || (lane >= 17u && lane <= 26u);
        uint32_t j = (lane < 16u) ? lane : (lane - 6u);   // ull slot in 168B block
#pragma unroll 4
        for (int it = 0; it < 16; ++it) {
            uint32_t eidx = 2u * (uint32_t)it + h;
            uint32_t s = __shfl_sync(F, sv, eidx);
            uint32_t d = __shfl_sync(F, dv, eidx);
            ull a = __ldg(Ps8 + (size_t)s * 16u + q);
            ull b = __ldg(Pd8 + (size_t)d * 16u + q);
            ull rr = add2(a, b);
            float lo, hi; unpack2(rr, lo, hi);
            float b0 = __shfl_sync(F, lo, 16);        // edge B float 0
            float ph = __shfl_up_sync(F, hi, 1);      // prev lane's hi (edge B realign)
            ull v = rr;                               // lanes 0..9: pairs of edge A
            if (lane == 10u)      v = pack2f(lo, b0); // (A20, B0)
            else if (lane >= 16u) v = pack2f(ph, lo); // (B(2q-1), B(2q))
            if (doStore)
                __stcs(outU + (size_t)it * 21u + j, v);
        }
    } else {
        const float* __restrict__ Ps = g_Ps;
        const float* __restrict__ Pd = g_Pd;
        for (uint32_t it = 0; it < nIt; ++it) {
            uint32_t s = __shfl_sync(F, sv, it);
            uint32_t d = __shfl_sync(F, dv, it);
            if (lane < C) {
                float v = __ldg(&Ps[(size_t)s * PROW + lane]) +
                          __ldg(&Pd[(size_t)d * PROW + lane]);
                out[(size_t)(e0 + it) * C + lane] = v;
            }
        }
    }
}

// ---------------------------------------------------------------------------
extern "C" void kernel_launch(void* const* d_in, const int* in_sizes, int n_in,
                              void* d_out, int out_size) {
    const float*    emb   = (const float*)d_in[0];
    const uint32_t* ei    = (const uint32_t*)d_in[1];
    const float*    Wsrc  = (const float*)d_in[2];
    const float*    Wdst  = (const float*)d_in[3];
    const float*    bfuse = (const float*)d_in[4];
    const float*    Wcls  = (const float*)d_in[5];
    const float*    bcls  = (const float*)d_in[6];
    float* out = (float*)d_out;

    int N = in_sizes[0] / D;          // 50000
    int E = in_sizes[1] / 2;          // 1600000

    int cblocks = (2 * D * C * 4) / 256 + 1;   // 84 compute + 1 detect/bias
    combine_kernel<<<cblocks, 256>>>(Wsrc, Wdst, Wcls, bfuse, bcls, ei);

    int nodesPerBlock = 8 * NPT;
    nodeproj_kernel<<<(N + nodesPerBlock - 1) / nodesPerBlock, 256>>>(emb, N);

    uint32_t warps  = ((uint32_t)E + 31u) / 32u;
    uint32_t blocks = (warps + 7u) / 8u;
    edge_kernel<<<blocks, 256>>>(ei, out, (uint32_t)E);
}

// round 8
// speedup vs baseline: 1.0276x; 1.0276x over previous
#include <cuda_runtime.h>
#include <cstdint>

#define D    128
#define C    21
#define PROW 32       // padded P-table row (floats) = one 128B line
#define MAXN 50000
#define NPT  8        // nodes per warp in nodeproj

typedef unsigned long long ull;

// Scratch (static device globals — no allocation allowed)
__device__ float g_WsT[C * 132];
__device__ float g_WdT[C * 132];
__device__ float g_bc[C];
__device__ float g_Ps [MAXN * PROW];   // normal rows: pairs (2m,2m+1)
__device__ float g_Pd [MAXN * PROW];
__device__ float g_PsR[MAXN * PROW];   // rotated rows: float i holds P[i+1] (i=0..19), float20 = P[0]
__device__ float g_PdR[MAXN * PROW];
__device__ int   g_is64;

#define CP 132

// ---- packed fp32x2 ops (sm_103a; PTX-only forms) ---------------------------
__device__ __forceinline__ ull fma2(ull a, ull b, ull c) {
    ull d;
    asm("fma.rn.f32x2 %0, %1, %2, %3;" : "=l"(d) : "l"(a), "l"(b), "l"(c));
    return d;
}
__device__ __forceinline__ ull add2(ull a, ull b) {
    ull d;
    asm("add.rn.f32x2 %0, %1, %2;" : "=l"(d) : "l"(a), "l"(b));
    return d;
}
__device__ __forceinline__ void unpack2(ull v, float& lo, float& hi) {
    uint32_t l, h;
    asm("mov.b64 {%0, %1}, %2;" : "=r"(l), "=r"(h) : "l"(v));
    lo = __uint_as_float(l); hi = __uint_as_float(h);
}
__device__ __forceinline__ float f2lo(ull v) {
    float lo, hi; unpack2(v, lo, hi); return lo;
}
__device__ __forceinline__ float f2sum(ull v) {
    float lo, hi; unpack2(v, lo, hi); return lo + hi;
}

// ---------------------------------------------------------------------------
// combine_kernel: no smem, no syncthreads. 8 lanes per output, direct __ldg,
// shfl-tree reduce. Last block: dtype detection + bias fold.
// ---------------------------------------------------------------------------
__global__ void __launch_bounds__(256) combine_kernel(const float* __restrict__ Wsrc,
                                                      const float* __restrict__ Wdst,
                                                      const float* __restrict__ Wcls,
                                                      const float* __restrict__ bfuse,
                                                      const float* __restrict__ bcls,
                                                      const uint32_t* __restrict__ ew) {
    if (blockIdx.x == gridDim.x - 1) {
        if (threadIdx.x < 32) {
            int lane = threadIdx.x;
            uint32_t v = 0;
#pragma unroll
            for (int i = 0; i < 8; i++)
                v |= ew[1 + 2 * (lane + 32 * i)];   // odd words: int64 high halves
#pragma unroll
            for (int o = 16; o; o >>= 1)
                v |= __shfl_xor_sync(0xffffffffu, v, o);
            if (lane == 0) g_is64 = (v == 0u) ? 1 : 0;
        } else if (threadIdx.x < 32 + C) {
            int c = threadIdx.x - 32;
            float acc = bcls[c];
#pragma unroll 8
            for (int j = 0; j < D; j++)
                acc = fmaf(__ldg(&bfuse[j]), __ldg(&Wcls[j * C + c]), acc);
            g_bc[c] = acc;
        }
        return;
    }

    int t = blockIdx.x * blockDim.x + threadIdx.x;   // 168 blocks * 256 = 43008 = 8*5376
    int o = t >> 3;                                  // output id in [0, 2*D*C)
    int p = t & 7;                                   // eighth of the K dim (16 elems)
    int m = o / (D * C);
    int r = o % (D * C);
    int k = r / C;
    int c = r % C;

    const float4* W4 = (const float4*)((m ? Wdst : Wsrc) + (size_t)k * D) + 4 * p;
    float acc = 0.f;
#pragma unroll
    for (int j = 0; j < 4; j++) {
        float4 w = __ldg(W4 + j);
        int e = 16 * p + 4 * j;
        acc = fmaf(w.x, __ldg(&Wcls[(e + 0) * C + c]), acc);
        acc = fmaf(w.y, __ldg(&Wcls[(e + 1) * C + c]), acc);
        acc = fmaf(w.z, __ldg(&Wcls[(e + 2) * C + c]), acc);
        acc = fmaf(w.w, __ldg(&Wcls[(e + 3) * C + c]), acc);
    }
    acc += __shfl_down_sync(0xffffffffu, acc, 4);
    acc += __shfl_down_sync(0xffffffffu, acc, 2);
    acc += __shfl_down_sync(0xffffffffu, acc, 1);
    if (p == 0)
        (m ? g_WdT : g_WsT)[c * CP + k] = acc;
}

// ---------------------------------------------------------------------------
// Per-node projection: warp = NPT nodes x (lane = class), f32x2 FMAs.
// Writes BOTH the normal and rotated table rows.
// ---------------------------------------------------------------------------
__global__ void __launch_bounds__(256) nodeproj_kernel(const float* __restrict__ emb, int N) {
    __shared__ __align__(16) float sWs[C * CP];
    __shared__ __align__(16) float sWd[C * CP];
    __shared__ float sbc[C];
    for (int i = threadIdx.x; i < C * CP; i += blockDim.x) {
        sWs[i] = g_WsT[i];
        sWd[i] = g_WdT[i];
    }
    if (threadIdx.x < C) sbc[threadIdx.x] = g_bc[threadIdx.x];
    __syncthreads();

    int wid  = threadIdx.x >> 5;
    int lane = threadIdx.x & 31;
    int n0   = (blockIdx.x * 8 + wid) * NPT;
    if (n0 >= N) return;

    int cc = (lane < C) ? lane : (C - 1);
    const ulonglong2* ws2 = (const ulonglong2*)(sWs + cc * CP);
    const ulonglong2* wd2 = (const ulonglong2*)(sWd + cc * CP);
    const ulonglong2* e2  = (const ulonglong2*)(emb + (size_t)n0 * D);

    ull as2[NPT], ad2[NPT];
#pragma unroll
    for (int j = 0; j < NPT; j++) { as2[j] = 0ull; ad2[j] = 0ull; }

    int nv = N - n0; if (nv > NPT) nv = NPT;

    if (nv == NPT) {
#pragma unroll
        for (int k = 0; k < D / 4; k++) {
            ulonglong2 ws = ws2[k];
            ulonglong2 wd = wd2[k];
#pragma unroll
            for (int j = 0; j < NPT; j++) {
                ulonglong2 ev = __ldg(e2 + (size_t)j * (D / 4) + k);  // warp broadcast
                as2[j] = fma2(ev.x, ws.x, as2[j]);
                as2[j] = fma2(ev.y, ws.y, as2[j]);
                ad2[j] = fma2(ev.x, wd.x, ad2[j]);
                ad2[j] = fma2(ev.y, wd.y, ad2[j]);
            }
        }
    } else {
        for (int k = 0; k < D / 4; k++) {
            ulonglong2 ws = ws2[k];
            ulonglong2 wd = wd2[k];
            for (int j = 0; j < nv; j++) {
                ulonglong2 ev = __ldg(e2 + (size_t)j * (D / 4) + k);
                as2[j] = fma2(ev.x, ws.x, as2[j]);
                as2[j] = fma2(ev.y, ws.y, as2[j]);
                ad2[j] = fma2(ev.x, wd.x, ad2[j]);
                ad2[j] = fma2(ev.y, wd.y, ad2[j]);
            }
        }
    }

    if (lane < C) {
        float bc = sbc[lane];
        int pos = (lane == 0) ? 20 : (lane - 1);   // rotated-row position of class `lane`
#pragma unroll
        for (int j = 0; j < NPT; j++) {
            if (j < nv) {
                size_t row = (size_t)(n0 + j) * PROW;
                float vs = f2sum(as2[j]) + bc;
                float vd = f2sum(ad2[j]);
                g_Ps [row + lane] = vs;
                g_Pd [row + lane] = vd;
                g_PsR[row + pos]  = vs;
                g_PdR[row + pos]  = vd;
            }
        }
    }
}

// ---------------------------------------------------------------------------
// Edge kernel: rotated-table scheme, MIO-minimal.
// Warp owns 32 edges. Each edge's 21 output floats = 10 aligned ull pairs +
// 1 straggler float. Even edges read normal rows (pairs (2m,2m+1)), odd edges
// read ROTATED rows (pairs (2m+1,2m+2); ull10.lo = P0) — so every lane's
// output ull is produced locally, no repack shfls. 11 rounds x 32 lane-slots
// cover 32 edges x 11 slots. Per round: 2 shfl + 2 LDG.64 + 2 pred. STG.
// ---------------------------------------------------------------------------
__global__ void __launch_bounds__(256) edge_kernel(const uint32_t* __restrict__ ew,
                                                   float* __restrict__ out,
                                                   uint32_t E) {
    const uint32_t F = 0xffffffffu;
    uint32_t wid  = threadIdx.x >> 5;
    uint32_t lane = threadIdx.x & 31;
    uint32_t warp = blockIdx.x * 8u + wid;
    uint32_t e0   = warp * 32u;
    if (e0 >= E) return;

    uint32_t myE = e0 + lane;
    bool have = (myE < E);
    uint32_t sv = 0, dv = 0;
    if (g_is64) {
        const uint2* ew2 = (const uint2*)ew;
        if (have) {
            sv = ew2[myE].x;
            dv = ew2[(size_t)E + myE].x;
        }
    } else {
        if (have) {
            sv = ew[myE];
            dv = ew[(size_t)E + myE];
        }
    }

    const ull* __restrict__ Ps8  = (const ull*)g_Ps;    // 16 ulls per row
    const ull* __restrict__ Pd8  = (const ull*)g_Pd;
    const ull* __restrict__ PsR8 = (const ull*)g_PsR;
    const ull* __restrict__ PdR8 = (const ull*)g_PdR;

    uint32_t nIt = E - e0; if (nIt > 32u) nIt = 32u;

    if (nIt == 32u) {
        char* wbase = (char*)(out + (size_t)e0 * C);   // 2688B-aligned
#pragma unroll
        for (uint32_t R = 0; R < 11u; ++R) {
            uint32_t t = 32u * R + lane;               // lane-slot 0..351
            uint32_t e = t / 11u;                      // edge 0..31
            uint32_t m = t - 11u * e;                  // ull slot 0..10
            uint32_t par = e & 1u;
            uint32_t s = __shfl_sync(F, sv, e);
            uint32_t d = __shfl_sync(F, dv, e);
            const ull* Pa = par ? PsR8 : Ps8;
            const ull* Pb = par ? PdR8 : Pd8;
            ull a = __ldg(Pa + (size_t)s * 16u + m);
            ull b = __ldg(Pb + (size_t)d * 16u + m);
            ull v = add2(a, b);
            if (m <= 9u) {
                // even e: floats (2m,2m+1) at byte 84e+8m; odd e: floats
                // (2m+1,2m+2) at byte 84e+4+8m. Both 8B-aligned.
                __stcs((ull*)(wbase + 84u * e + 4u * par + 8u * m), v);
            } else {
                // straggler: even -> P20 at +80; odd -> P0 at +0
                __stcs((float*)(wbase + 84u * e + (par ? 0u : 80u)), f2lo(v));
            }
        }
    } else {
        const float* __restrict__ Ps = g_Ps;
        const float* __restrict__ Pd = g_Pd;
        for (uint32_t it = 0; it < nIt; ++it) {
            uint32_t s = __shfl_sync(F, sv, it);
            uint32_t d = __shfl_sync(F, dv, it);
            if (lane < C) {
                float v = __ldg(&Ps[(size_t)s * PROW + lane]) +
                          __ldg(&Pd[(size_t)d * PROW + lane]);
                out[(size_t)(e0 + it) * C + lane] = v;
            }
        }
    }
}

// ---------------------------------------------------------------------------
extern "C" void kernel_launch(void* const* d_in, const int* in_sizes, int n_in,
                              void* d_out, int out_size) {
    const float*    emb   = (const float*)d_in[0];
    const uint32_t* ei    = (const uint32_t*)d_in[1];
    const float*    Wsrc  = (const float*)d_in[2];
    const float*    Wdst  = (const float*)d_in[3];
    const float*    bfuse = (const float*)d_in[4];
    const float*    Wcls  = (const float*)d_in[5];
    const float*    bcls  = (const float*)d_in[6];
    float* out = (float*)d_out;

    int N = in_sizes[0] / D;          // 50000
    int E = in_sizes[1] / 2;          // 1600000

    int cblocks = (2 * D * C * 8) / 256 + 1;   // 168 compute + 1 detect/bias
    combine_kernel<<<cblocks, 256>>>(Wsrc, Wdst, Wcls, bfuse, bcls, ei);

    int nodesPerBlock = 8 * NPT;
    nodeproj_kernel<<<(N + nodesPerBlock - 1) / nodesPerBlock, 256>>>(emb, N);

    uint32_t warps  = ((uint32_t)E + 31u) / 32u;
    uint32_t blocks = (warps + 7u) / 8u;
    edge_kernel<<<blocks, 256>>>(ei, out, (uint32_t)E);
}